// round 5
// baseline (speedup 1.0000x reference)
#include <cuda_runtime.h>
#include <cuda_bf16.h>
#include <mma.h>
#include <cstdint>
#include <math.h>

using namespace nvcuda;

#define N_NODES 50000
#define N_EDGES 800000
#define MULC 32
#define RADC 8
#define FCC 64

#define INV_SQRT_MUL 0.17677669529663687f
#define INV_SQRT_RAD 0.35355339059327373f
#define INV_SQRT_FC  0.125f
#define INV_SQRT_NN  0.25f
#define INV_SQRT_2MUL 0.125f
#define INV_SQRT3_C 0.5773502691896258f
#define MIX_C 0.9238795325112867f
#define MIX_S 0.3826834323650898f

typedef unsigned long long u64;
typedef unsigned int u32;

// ---------------- f32x2 helpers (out_kernel) ---------------------------------
__device__ __forceinline__ u64 pack2(float lo, float hi) {
    u64 d; asm("mov.b64 %0, {%1, %2};" : "=l"(d) : "f"(lo), "f"(hi)); return d;
}
__device__ __forceinline__ float2 unpack2(u64 v) {
    float lo, hi; asm("mov.b64 {%0, %1}, %2;" : "=f"(lo), "=f"(hi) : "l"(v));
    return make_float2(lo, hi);
}
__device__ __forceinline__ u64 fma2(u64 a, u64 b, u64 c) {
    u64 d; asm("fma.rn.f32x2 %0, %1, %2, %3;" : "=l"(d) : "l"(a), "l"(b), "l"(c));
    return d;
}
__device__ __forceinline__ u64 ld2(const float2* p) {
    float2 v = *p;
    u64 d; asm("mov.b64 %0, {%1, %2};" : "=l"(d) : "f"(v.x), "f"(v.y)); return d;
}

// gelu(x) = x * sigmoid(2u),  u = 0.79788456(x + 0.044715 x^3)
__device__ __forceinline__ float gelu_fast(float x) {
    float x2 = x * x;
    float arg = x * (-1.5957691216057308f - 0.07135481627352344f * x2); // -2u
    float p = __expf(arg);
    return __fdividef(x, 1.0f + p);
}

// pack (lo_arg, hi_arg) as bf16x2: element0 (low 16 bits) = lo_val
__device__ __forceinline__ unsigned cvt_bf16x2(float hi_val, float lo_val) {
    unsigned r; asm("cvt.rn.bf16x2.f32 %0, %1, %2;" : "=r"(r) : "f"(hi_val), "f"(lo_val));
    return r;
}

// ---------------- scratch ----------------------------------------------------
__device__ __align__(16) float g_f0[N_NODES * MULC];
__device__ __align__(16) float g_f1[N_NODES * 3 * MULC];
__device__ __align__(16) float g_self0[N_NODES * MULC];
__device__ __align__(16) float g_self1[N_NODES * 3 * MULC];
__device__ __align__(16) float g_n0[N_NODES * 2 * MULC];
__device__ __align__(16) float g_n1[N_NODES * 3 * 2 * MULC];

// ---------------- kernel 1: node pre-transforms + accumulator zeroing -------
#define PRE_BLOCKS 6250
#define ZERO_BLOCKS 1088
__global__ void node_pre_kernel(const float* __restrict__ node_s,
                                const float* __restrict__ node_v,
                                const float* __restrict__ Wf0,
                                const float* __restrict__ Ws0,
                                const float* __restrict__ Wf1,
                                const float* __restrict__ Ws1) {
    if (blockIdx.x >= PRE_BLOCKS) {
        int i = (blockIdx.x - PRE_BLOCKS) * blockDim.x + threadIdx.x;
        int stride = ZERO_BLOCKS * blockDim.x;
        float4* p0 = (float4*)g_n0;
        float4* p1 = (float4*)g_n1;
        const float4 z = make_float4(0.f, 0.f, 0.f, 0.f);
        for (int k = i; k < N_NODES * 16; k += stride) p0[k] = z;
        for (int k = i; k < N_NODES * 48; k += stride) p1[k] = z;
        return;
    }

    __shared__ float sWf0[1024], sWs0[1024], sWf1[1024], sWs1[1024];
    for (int i = threadIdx.x; i < 1024; i += blockDim.x) {
        sWf0[i] = Wf0[i] * INV_SQRT_MUL;
        sWs0[i] = Ws0[i] * (INV_SQRT_MUL * MIX_C);
        sWf1[i] = Wf1[i] * INV_SQRT_MUL;
        sWs1[i] = Ws1[i] * (INV_SQRT_MUL * MIX_C);
    }
    __syncthreads();

    int lane = threadIdx.x & 31;
    int warp = threadIdx.x >> 5;
    int n = blockIdx.x * (blockDim.x >> 5) + warp;
    if (n >= N_NODES) return;

    float sv  = node_s[n * 32 + lane];
    float vx  = node_v[n * 96 + lane * 3 + 0];
    float vy  = node_v[n * 96 + lane * 3 + 1];
    float vz  = node_v[n * 96 + lane * 3 + 2];

    float f0 = 0.f, s0 = 0.f;
    float f1x = 0.f, f1y = 0.f, f1z = 0.f;
    float s1x = 0.f, s1y = 0.f, s1z = 0.f;

    #pragma unroll 8
    for (int u = 0; u < 32; u++) {
        float su = __shfl_sync(0xffffffffu, sv, u);
        float ux = __shfl_sync(0xffffffffu, vx, u);
        float uy = __shfl_sync(0xffffffffu, vy, u);
        float uz = __shfl_sync(0xffffffffu, vz, u);
        float wf0 = sWf0[u * 32 + lane];
        float ws0 = sWs0[u * 32 + lane];
        float wf1 = sWf1[u * 32 + lane];
        float ws1 = sWs1[u * 32 + lane];
        f0 += su * wf0;  s0 += su * ws0;
        f1x += ux * wf1; f1y += uy * wf1; f1z += uz * wf1;
        s1x += ux * ws1; s1y += uy * ws1; s1z += uz * ws1;
    }

    g_f0[n * 32 + lane] = f0;
    g_self0[n * 32 + lane] = s0;
    g_f1[n * 96 + 0 * 32 + lane] = f1x;
    g_f1[n * 96 + 1 * 32 + lane] = f1y;
    g_f1[n * 96 + 2 * 32 + lane] = f1z;
    g_self1[n * 96 + 0 * 32 + lane] = s1x;
    g_self1[n * 96 + 1 * 32 + lane] = s1y;
    g_self1[n * 96 + 2 * 32 + lane] = s1z;
}

// ---------------- kernel 2: edge phase (wmma bf16 hi/lo, warp-autonomous) ----
// Each warp owns a 16-edge tile. GEMMs: [16,16(8)]x[16,64] -> gelu ->
// [16,64]x[64,64] -> gelu -> [16,64]x[64,128] -> scatter.
#define EDGE_WARPS 12
#define NTILES (N_EDGES / 16)    /* 50000 */

// element strides
#define A0S 24     /* bf16 */
#define AS  72     /* bf16 */
#define CS  76     /* f32  */
#define B0S 72
#define W1S 72
#define WPS 136

// smem byte offsets
#define OFF_B0H 0
#define OFF_B0L (OFF_B0H + 16 * B0S * 2)          /* 2304 */
#define OFF_W1H (OFF_B0L + 16 * B0S * 2)          /* 4608 */
#define OFF_W1L (OFF_W1H + 64 * W1S * 2)          /* 13824 */
#define OFF_WPH (OFF_W1L + 64 * W1S * 2)          /* 23040 */
#define OFF_WPL (OFF_WPH + 64 * WPS * 2)          /* 40448 */
#define OFF_PW  (OFF_WPL + 64 * WPS * 2)          /* 57856 */
#define PW_A0H  0
#define PW_A0L  (PW_A0H + 16 * A0S * 2)           /* 768 */
#define PW_AHI  (PW_A0L + 16 * A0S * 2)           /* 1536 */
#define PW_ALO  (PW_AHI + 16 * AS * 2)            /* 3840 */
#define PW_C    (PW_ALO + 16 * AS * 2)            /* 6144 */
#define PW_META (PW_C + 16 * CS * 4)              /* 11008 */
#define PW_SIZE 11392                              /* 128-aligned */
#define EDGE_SMEM_BYTES (OFF_PW + EDGE_WARPS * PW_SIZE)   /* 194560 */

// gelu + bf16 hi/lo split: Cb[16][CS] f32 -> hi/lo bf16 [16][AS]
__device__ __forceinline__ void gelu_split_epilogue(const float* Cb,
                                                    __nv_bfloat16* hi,
                                                    __nv_bfloat16* lo,
                                                    int lane) {
    int r = lane >> 1, h = lane & 1;
    const float* row = Cb + r * CS + h * 32;
    unsigned* hrow = (unsigned*)(hi + r * AS + h * 32);
    unsigned* lrow = (unsigned*)(lo + r * AS + h * 32);
    #pragma unroll
    for (int cp = 0; cp < 16; cp++) {
        float2 v = *(const float2*)(row + 2 * cp);
        float g0 = gelu_fast(v.x);
        float g1 = gelu_fast(v.y);
        unsigned hp = cvt_bf16x2(g1, g0);
        float h0 = __uint_as_float(hp << 16);
        float h1 = __uint_as_float(hp & 0xffff0000u);
        unsigned lp = cvt_bf16x2(g1 - h1, g0 - h0);
        hrow[cp] = hp;
        lrow[cp] = lp;
    }
}

__global__ __launch_bounds__(EDGE_WARPS * 32, 1)
void edge_kernel(const float* __restrict__ sh0,
                 const float* __restrict__ sh1,
                 const float* __restrict__ edge_scalar,
                 const int* __restrict__ edge_src,
                 const int* __restrict__ edge_dst,
                 const float* __restrict__ mlp_w0,
                 const float* __restrict__ mlp_w1,
                 const float* __restrict__ wp0,
                 const float* __restrict__ wp1,
                 const float* __restrict__ wp2,
                 const float* __restrict__ wp3) {
    extern __shared__ char sm[];
    const int tid  = threadIdx.x;
    const int lane = tid & 31;
    const int wid  = tid >> 5;

    __nv_bfloat16* sB0h = (__nv_bfloat16*)(sm + OFF_B0H);
    __nv_bfloat16* sB0l = (__nv_bfloat16*)(sm + OFF_B0L);
    __nv_bfloat16* sW1h = (__nv_bfloat16*)(sm + OFF_W1H);
    __nv_bfloat16* sW1l = (__nv_bfloat16*)(sm + OFF_W1L);
    __nv_bfloat16* sWPh = (__nv_bfloat16*)(sm + OFF_WPH);
    __nv_bfloat16* sWPl = (__nv_bfloat16*)(sm + OFF_WPL);

    // ---- weight prep (hi/lo bf16 split, scales folded) -----------------------
    for (int i = tid; i < 16 * 64; i += blockDim.x) {
        int k = i >> 6, n = i & 63;
        float x = (k < 8) ? mlp_w0[k * 64 + n] * INV_SQRT_RAD : 0.0f;
        __nv_bfloat16 h = __float2bfloat16_rn(x);
        __nv_bfloat16 l = __float2bfloat16_rn(x - __bfloat162float(h));
        sB0h[k * B0S + n] = h;
        sB0l[k * B0S + n] = l;
    }
    for (int i = tid; i < 64 * 64; i += blockDim.x) {
        int k = i >> 6, n = i & 63;
        float x = mlp_w1[k * 64 + n] * INV_SQRT_FC;
        __nv_bfloat16 h = __float2bfloat16_rn(x);
        __nv_bfloat16 l = __float2bfloat16_rn(x - __bfloat162float(h));
        sW1h[k * W1S + n] = h;
        sW1l[k * W1S + n] = l;
    }
    const float wpsc = INV_SQRT_FC * INV_SQRT_NN;
    for (int i = tid; i < 64 * 128; i += blockDim.x) {
        int k = i >> 7, n = i & 127;
        int p = n >> 5, c = n & 31;
        const float* wpp = (p == 0) ? wp0 : (p == 1) ? wp1 : (p == 2) ? wp2 : wp3;
        float x = wpp[k * 32 + c] * wpsc;
        __nv_bfloat16 h = __float2bfloat16_rn(x);
        __nv_bfloat16 l = __float2bfloat16_rn(x - __bfloat162float(h));
        sWPh[k * WPS + n] = h;
        sWPl[k * WPS + n] = l;
    }
    // zero a0 cols 8..15 for every warp (once)
    for (int i = tid; i < EDGE_WARPS * 16 * 8; i += blockDim.x) {
        int w = i >> 7;
        int r = (i >> 3) & 15;
        int c = 8 + (i & 7);
        char* pw = sm + OFF_PW + w * PW_SIZE;
        ((__nv_bfloat16*)(pw + PW_A0H))[r * A0S + c] = __float2bfloat16_rn(0.0f);
        ((__nv_bfloat16*)(pw + PW_A0L))[r * A0S + c] = __float2bfloat16_rn(0.0f);
    }
    __syncthreads();

    char* pw = sm + OFF_PW + wid * PW_SIZE;
    __nv_bfloat16* a0h = (__nv_bfloat16*)(pw + PW_A0H);
    __nv_bfloat16* a0l = (__nv_bfloat16*)(pw + PW_A0L);
    __nv_bfloat16* aHi = (__nv_bfloat16*)(pw + PW_AHI);
    __nv_bfloat16* aLo = (__nv_bfloat16*)(pw + PW_ALO);
    float* Cb   = (float*)(pw + PW_C);
    int*   msrc = (int*)(pw + PW_META);
    int*   mdst = msrc + 16;
    float* msh0 = (float*)(mdst + 16);
    float* msh1 = msh0 + 16;

    typedef wmma::fragment<wmma::matrix_a, 16, 16, 16, __nv_bfloat16, wmma::row_major> FragA;
    typedef wmma::fragment<wmma::matrix_b, 16, 16, 16, __nv_bfloat16, wmma::row_major> FragB;
    typedef wmma::fragment<wmma::accumulator, 16, 16, 16, float> FragC;

    for (int t = blockIdx.x * EDGE_WARPS + wid; t < NTILES; t += gridDim.x * EDGE_WARPS) {
        const int base = t * 16;

        // ---- stage meta + ES --------------------------------------------------
        if (lane < 16) {
            msrc[lane] = edge_src[base + lane];
            mdst[lane] = edge_dst[base + lane];
            msh0[lane] = sh0[base + lane];
        }
        for (int j = lane; j < 48; j += 32) msh1[j] = sh1[base * 3 + j];

        {
            int e = lane >> 1, kh = lane & 1;
            float4 es = __ldg((const float4*)(edge_scalar + (size_t)(base + e) * 8 + kh * 4));
            unsigned hp0 = cvt_bf16x2(es.y, es.x);
            unsigned lp0 = cvt_bf16x2(es.y - __uint_as_float(hp0 & 0xffff0000u),
                                      es.x - __uint_as_float(hp0 << 16));
            unsigned hp1 = cvt_bf16x2(es.w, es.z);
            unsigned lp1 = cvt_bf16x2(es.w - __uint_as_float(hp1 & 0xffff0000u),
                                      es.z - __uint_as_float(hp1 << 16));
            unsigned* dh = (unsigned*)(a0h + e * A0S + kh * 4);
            unsigned* dl = (unsigned*)(a0l + e * A0S + kh * 4);
            dh[0] = hp0; dh[1] = hp1;
            dl[0] = lp0; dl[1] = lp1;
        }
        __syncwarp();

        // ---- GEMM0: C[16,64] = a0 @ B0 ----------------------------------------
        {
            FragA fah, fal;
            wmma::load_matrix_sync(fah, a0h, A0S);
            wmma::load_matrix_sync(fal, a0l, A0S);
            #pragma unroll
            for (int j = 0; j < 4; j++) {
                FragC acc;
                wmma::fill_fragment(acc, 0.0f);
                FragB fbh, fbl;
                wmma::load_matrix_sync(fbh, sB0h + j * 16, B0S);
                wmma::load_matrix_sync(fbl, sB0l + j * 16, B0S);
                wmma::mma_sync(acc, fah, fbh, acc);
                wmma::mma_sync(acc, fah, fbl, acc);
                wmma::mma_sync(acc, fal, fbh, acc);
                wmma::store_matrix_sync(Cb + j * 16, acc, CS, wmma::mem_row_major);
            }
        }
        __syncwarp();
        gelu_split_epilogue(Cb, aHi, aLo, lane);
        __syncwarp();

        // ---- GEMM1: C[16,64] = h0 @ W1 ----------------------------------------
        {
            FragA fah[4], fal[4];
            #pragma unroll
            for (int kt = 0; kt < 4; kt++) {
                wmma::load_matrix_sync(fah[kt], aHi + kt * 16, AS);
                wmma::load_matrix_sync(fal[kt], aLo + kt * 16, AS);
            }
            #pragma unroll
            for (int j = 0; j < 4; j++) {
                FragC acc;
                wmma::fill_fragment(acc, 0.0f);
                #pragma unroll
                for (int kt = 0; kt < 4; kt++) {
                    FragB fbh, fbl;
                    wmma::load_matrix_sync(fbh, sW1h + kt * 16 * W1S + j * 16, W1S);
                    wmma::load_matrix_sync(fbl, sW1l + kt * 16 * W1S + j * 16, W1S);
                    wmma::mma_sync(acc, fah[kt], fbh, acc);
                    wmma::mma_sync(acc, fah[kt], fbl, acc);
                    wmma::mma_sync(acc, fal[kt], fbh, acc);
                }
                wmma::store_matrix_sync(Cb + j * 16, acc, CS, wmma::mem_row_major);
            }
        }
        __syncwarp();
        gelu_split_epilogue(Cb, aHi, aLo, lane);
        __syncwarp();

        // ---- projections + scatter, two 64-col passes --------------------------
        FragA fah[4], fal[4];
        #pragma unroll
        for (int kt = 0; kt < 4; kt++) {
            wmma::load_matrix_sync(fah[kt], aHi + kt * 16, AS);
            wmma::load_matrix_sync(fal[kt], aLo + kt * 16, AS);
        }

        #pragma unroll
        for (int pass = 0; pass < 2; pass++) {
            #pragma unroll
            for (int j = 0; j < 4; j++) {
                FragC acc;
                wmma::fill_fragment(acc, 0.0f);
                int ncol = pass * 64 + j * 16;
                #pragma unroll
                for (int kt = 0; kt < 4; kt++) {
                    FragB fbh, fbl;
                    wmma::load_matrix_sync(fbh, sWPh + kt * 16 * WPS + ncol, WPS);
                    wmma::load_matrix_sync(fbl, sWPl + kt * 16 * WPS + ncol, WPS);
                    wmma::mma_sync(acc, fah[kt], fbh, acc);
                    wmma::mma_sync(acc, fah[kt], fbl, acc);
                    wmma::mma_sync(acc, fal[kt], fbh, acc);
                }
                wmma::store_matrix_sync(Cb + j * 16, acc, CS, wmma::mem_row_major);
            }
            __syncwarp();

            if (pass == 0) {
                // cols 0-31 = w0 term, cols 32-63 = w1 term
                #pragma unroll 4
                for (int e = 0; e < 16; e++) {
                    const float* row = Cb + e * CS;
                    float v0 = row[lane];
                    float v1 = row[32 + lane];
                    int src = msrc[e], dst = mdst[e];
                    float s0 = msh0[e];
                    float shx = msh1[e * 3 + 0];
                    float shy = msh1[e * 3 + 1];
                    float shz = msh1[e * 3 + 2];
                    float e0 = g_f0[src * 32 + lane];
                    atomicAdd(g_n0 + dst * 64 + lane, v0 * e0 * s0);
                    float tv = v1 * e0;
                    float* p = g_n1 + dst * 192 + lane;
                    atomicAdd(p,       tv * shx);
                    atomicAdd(p + 64,  tv * shy);
                    atomicAdd(p + 128, tv * shz);
                }
            } else {
                // cols 0-31 = w2 term, cols 32-63 = w3 term
                #pragma unroll 4
                for (int e = 0; e < 16; e++) {
                    const float* row = Cb + e * CS;
                    float v2 = row[lane];
                    float v3 = row[32 + lane];
                    int src = msrc[e], dst = mdst[e];
                    float s0 = msh0[e];
                    float shx = msh1[e * 3 + 0];
                    float shy = msh1[e * 3 + 1];
                    float shz = msh1[e * 3 + 2];
                    const float* f1 = g_f1 + src * 96 + lane;
                    float fx = f1[0], fy = f1[32], fz = f1[64];
                    float t2 = v2 * s0;
                    float* p = g_n1 + dst * 192 + 32 + lane;
                    atomicAdd(p,       t2 * fx);
                    atomicAdd(p + 64,  t2 * fy);
                    atomicAdd(p + 128, t2 * fz);
                    float d = fx * shx + fy * shy + fz * shz;
                    atomicAdd(g_n0 + dst * 64 + 32 + lane, v3 * d * INV_SQRT3_C);
                }
            }
            __syncwarp();
        }
    }
}

// ---------------- kernel 3: output transform ---------------------------------
#define OUT_WARPS 8
#define OUT_SMEM_BYTES ((2048 + 2048) * 4 + OUT_WARPS * 1024 * 4)

__global__ __launch_bounds__(OUT_WARPS * 32, 2)
void out_kernel(const float* __restrict__ Wout0,
                const float* __restrict__ Wout1,
                float* __restrict__ out) {
    extern __shared__ float smf[];
    float2* sW0t = (float2*)smf;
    float2* sW1t = (float2*)(smf + 2048);
    float*  sStg = smf + 4096;

    const float osc = MIX_S * INV_SQRT_2MUL;
    for (int i = threadIdx.x; i < 1024; i += blockDim.x) {
        int kp = i >> 5, c = i & 31;
        sW0t[i] = make_float2(Wout0[(2 * kp) * 32 + c] * osc,
                              Wout0[(2 * kp + 1) * 32 + c] * osc);
        sW1t[i] = make_float2(Wout1[(2 * kp) * 32 + c] * osc,
                              Wout1[(2 * kp + 1) * 32 + c] * osc);
    }
    __syncthreads();

    const int lane = threadIdx.x & 31;
    const int warp = threadIdx.x >> 5;
    float* stg = sStg + warp * 1024;

    int gw = blockIdx.x * OUT_WARPS + warp;
    int nw = gridDim.x * OUT_WARPS;
    const int NG = N_NODES / 4;

    for (int g = gw; g < NG; g += nw) {
        const int nb = g * 4;

        #pragma unroll
        for (int m = 0; m < 4; m++) {
            const float* n0s = g_n0 + (nb + m) * 64;
            const float* n1s = g_n1 + (nb + m) * 192;
            float* s = stg + m * 256;
            s[lane]      = n0s[lane];
            s[32 + lane] = n0s[32 + lane];
            #pragma unroll
            for (int i = 0; i < 3; i++) {
                s[64 + i * 64 + lane]      = n1s[i * 64 + lane];
                s[64 + i * 64 + 32 + lane] = n1s[i * 64 + 32 + lane];
            }
        }
        __syncwarp();

        u64 accS[4];
        #pragma unroll
        for (int m = 0; m < 4; m++)
            accS[m] = pack2(g_self0[(nb + m) * 32 + lane], 0.0f);
        #pragma unroll 8
        for (int kp = 0; kp < 32; kp++) {
            u64 w2 = ld2(sW0t + kp * 32 + lane);
            #pragma unroll
            for (int m = 0; m < 4; m++) {
                u64 h2 = ld2((const float2*)(stg + m * 256 + 2 * kp));
                accS[m] = fma2(w2, h2, accS[m]);
            }
        }
        #pragma unroll
        for (int m = 0; m < 4; m++) {
            float2 tt = unpack2(accS[m]);
            out[(nb + m) * 128 + lane] = tt.x + tt.y;
        }

        u64 accV[4][3];
        #pragma unroll
        for (int m = 0; m < 4; m++)
            #pragma unroll
            for (int i = 0; i < 3; i++)
                accV[m][i] = pack2(g_self1[(nb + m) * 96 + i * 32 + lane], 0.0f);
        #pragma unroll 4
        for (int kp = 0; kp < 32; kp++) {
            u64 w2 = ld2(sW1t + kp * 32 + lane);
            #pragma unroll
            for (int m = 0; m < 4; m++) {
                const float* s = stg + m * 256 + 64;
                u64 h0 = ld2((const float2*)(s + 0 * 64 + 2 * kp));
                u64 h1 = ld2((const float2*)(s + 1 * 64 + 2 * kp));
                u64 h2v = ld2((const float2*)(s + 2 * 64 + 2 * kp));
                accV[m][0] = fma2(w2, h0, accV[m][0]);
                accV[m][1] = fma2(w2, h1, accV[m][1]);
                accV[m][2] = fma2(w2, h2v, accV[m][2]);
            }
        }
        #pragma unroll
        for (int m = 0; m < 4; m++) {
            #pragma unroll
            for (int i = 0; i < 3; i++) {
                float2 tt = unpack2(accV[m][i]);
                out[(nb + m) * 128 + 32 + lane * 3 + i] = tt.x + tt.y;
            }
        }
    }
}

// ---------------- launch -------------------------------------------------------
extern "C" void kernel_launch(void* const* d_in, const int* in_sizes, int n_in,
                              void* d_out, int out_size) {
    const float* node_s      = (const float*)d_in[0];
    const float* node_v      = (const float*)d_in[1];
    const float* sh0         = (const float*)d_in[2];
    const float* sh1         = (const float*)d_in[3];
    const float* edge_scalar = (const float*)d_in[4];
    const int*   edge_src    = (const int*)d_in[5];
    const int*   edge_dst    = (const int*)d_in[6];
    const float* W_feat0     = (const float*)d_in[7];
    const float* W_self0     = (const float*)d_in[8];
    const float* W_feat1     = (const float*)d_in[9];
    const float* W_self1     = (const float*)d_in[10];
    const float* mlp_w0      = (const float*)d_in[11];
    const float* mlp_w1      = (const float*)d_in[12];
    const float* wp0         = (const float*)d_in[13];
    const float* wp1         = (const float*)d_in[14];
    const float* wp2         = (const float*)d_in[15];
    const float* wp3         = (const float*)d_in[16];
    const float* W_out0      = (const float*)d_in[17];
    const float* W_out1      = (const float*)d_in[18];
    float* out = (float*)d_out;

    node_pre_kernel<<<PRE_BLOCKS + ZERO_BLOCKS, 256>>>(node_s, node_v,
                                                       W_feat0, W_self0,
                                                       W_feat1, W_self1);

    cudaFuncSetAttribute(edge_kernel,
                         cudaFuncAttributeMaxDynamicSharedMemorySize,
                         EDGE_SMEM_BYTES);
    edge_kernel<<<148, EDGE_WARPS * 32, EDGE_SMEM_BYTES>>>(
        sh0, sh1, edge_scalar, edge_src, edge_dst,
        mlp_w0, mlp_w1, wp0, wp1, wp2, wp3);

    cudaFuncSetAttribute(out_kernel,
                         cudaFuncAttributeMaxDynamicSharedMemorySize,
                         OUT_SMEM_BYTES);
    out_kernel<<<391, OUT_WARPS * 32, OUT_SMEM_BYTES>>>(W_out0, W_out1, out);
}